// round 3
// baseline (speedup 1.0000x reference)
#include <cuda_runtime.h>
#include <cstdint>

// ---------------------------------------------------------------------------
// GCN 2-layer:  out = scatter_sum( relu( scatter_sum( X@W1 ) ) @ W2 )
//   X: [100000, 256] f32, edges: [2, 3200000] (int64 or int32),
//   W1: [256,128], W2: [128,64], out: [100000, 64] f32
//
// Design: CSR build (hist/scan/fill) -> packed-f32x2 GEMM -> warp-gather
// aggregation (register accumulators, no float atomics, each row written once).
// ---------------------------------------------------------------------------

#define MAX_NODES 100000
#define MAX_EDGES 3200000
#define HID 128
#define ODIM 64

// Scratch (device globals: no allocation allowed)
__device__ __align__(16) float g_support1[(size_t)MAX_NODES * HID];   // X@W1
__device__ __align__(16) float g_h1[(size_t)MAX_NODES * HID];         // agg layer 1
__device__ __align__(16) float g_support2[(size_t)MAX_NODES * ODIM];  // relu(h1)@W2
__device__ int g_count[MAX_NODES];
__device__ int g_rowptr[MAX_NODES + 1];
__device__ int g_cursor[MAX_NODES];
__device__ int g_colidx[MAX_EDGES];
__device__ int g_is_i64;

// ---------------------------------------------------------------------------
// dtype detect: int64 edge data has all-zero high words (values in [0, 1e5))
// ---------------------------------------------------------------------------
__global__ void detect_kernel(const unsigned int* __restrict__ w, int nwords) {
    int ok = 1;
    for (int i = 1; i < nwords; i += 2)
        if (w[i] != 0u) { ok = 0; break; }
    g_is_i64 = ok;
}

__global__ void zero_count_kernel(int n) {
    int i = blockIdx.x * blockDim.x + threadIdx.x;
    if (i < n) g_count[i] = 0;
}

// ---------------------------------------------------------------------------
// CSR build
// ---------------------------------------------------------------------------
__global__ __launch_bounds__(256) void hist_kernel(const void* __restrict__ eptr,
                                                   long long n_edges) {
    long long i = (long long)blockIdx.x * blockDim.x + threadIdx.x;
    long long stride = (long long)gridDim.x * blockDim.x;
    if (g_is_i64) {
        const long long* E = (const long long*)eptr;
        for (; i < n_edges; i += stride) atomicAdd(&g_count[(int)E[i]], 1);
    } else {
        const int* E = (const int*)eptr;
        for (; i < n_edges; i += stride) atomicAdd(&g_count[E[i]], 1);
    }
}

// Single-block exclusive scan of g_count -> g_rowptr (+ cursor init).
__global__ __launch_bounds__(1024) void scan_kernel(int n) {
    __shared__ int s[1024];
    const int t = threadIdx.x;
    const int chunk = (n + 1023) / 1024;
    const int lo = t * chunk;
    const int hi = min(lo + chunk, n);

    int sum = 0;
    for (int i = lo; i < hi; i++) sum += g_count[i];
    s[t] = sum;
    __syncthreads();
#pragma unroll
    for (int off = 1; off < 1024; off <<= 1) {
        int v = (t >= off) ? s[t - off] : 0;
        __syncthreads();
        s[t] += v;
        __syncthreads();
    }
    int run = s[t] - sum;  // exclusive offset of this chunk
    for (int i = lo; i < hi; i++) {
        g_rowptr[i] = run;
        g_cursor[i] = run;
        run += g_count[i];
    }
    if (t == 1023) g_rowptr[n] = s[1023];
}

__global__ __launch_bounds__(256) void fill_kernel(const void* __restrict__ eptr,
                                                   long long n_edges) {
    long long i = (long long)blockIdx.x * blockDim.x + threadIdx.x;
    long long stride = (long long)gridDim.x * blockDim.x;
    if (g_is_i64) {
        const long long* E = (const long long*)eptr;
        for (; i < n_edges; i += stride) {
            int row = (int)E[i];
            int col = (int)E[n_edges + i];
            g_colidx[atomicAdd(&g_cursor[row], 1)] = col;
        }
    } else {
        const int* E = (const int*)eptr;
        for (; i < n_edges; i += stride) {
            int row = E[i];
            int col = E[n_edges + i];
            g_colidx[atomicAdd(&g_cursor[row], 1)] = col;
        }
    }
}

// ---------------------------------------------------------------------------
// Packed-f32x2 GEMM: out[n_rows, NCOL] = act(X[n_rows, K]) @ W[K, NCOL]
//
// K is packed pairwise into 64-bit lanes: acc holds (sum over even k, sum over
// odd k); one fma.rn.f32x2 per 2 scalar FMAs; lo+hi summed at epilogue.
// x pairs and w pairs are contiguous in smem -> loaded directly, no packing.
//
// Thread layout: col = tid % NCOL, slot = tid / NCOL; 32 rows per block.
// sWTp[c][t] = (W[k0+2t][c], W[k0+2t+1][c]); rows padded to 34 ull so
// LDS.128 quarter-warp phases hit 32 distinct banks (stride 68 words ≡ 4).
// ---------------------------------------------------------------------------
__device__ __forceinline__ void fma2(unsigned long long& acc,
                                     unsigned long long a,
                                     unsigned long long b) {
    asm("fma.rn.f32x2 %0, %1, %2, %0;" : "+l"(acc) : "l"(a), "l"(b));
}

template <int K, int NCOL, bool RELU>
__device__ __forceinline__ void gemm_body(const float* __restrict__ X,
                                          const float* __restrict__ W,
                                          float* __restrict__ out, int n_rows) {
    constexpr int KT = 64;                 // k-tile (32 pairs)
    constexpr int RPB = 32;                // rows per block
    constexpr int SLOTS = 256 / NCOL;
    constexpr int RPT = RPB / SLOTS;       // HID: 8 rows/thread, ODIM: 4
    constexpr int WROW = KT / 2 + 2;       // 34 ull, 16B-aligned, conflict-free

    __shared__ float sX[RPB][KT];                      // 8 KB
    __shared__ unsigned long long sWTp[NCOL][WROW];    // <= 34 KB

    const int tid = threadIdx.x;
    const int col = tid % NCOL;
    const int slot = tid / NCOL;
    const int row0 = blockIdx.x * RPB;

    unsigned long long acc[RPT];
#pragma unroll
    for (int j = 0; j < RPT; j++) acc[j] = 0ull;

    for (int k0 = 0; k0 < K; k0 += KT) {
        // W tile -> k-pair-packed, transposed smem
        for (int i = tid; i < (KT / 2) * NCOL; i += 256) {
            int t = i / NCOL, c = i % NCOL;
            float w0 = W[(k0 + 2 * t) * NCOL + c];
            float w1 = W[(k0 + 2 * t + 1) * NCOL + c];
            unsigned long long p;
            asm("mov.b64 %0, {%1, %2};" : "=l"(p)
                : "r"(__float_as_uint(w0)), "r"(__float_as_uint(w1)));
            sWTp[c][t] = p;
        }
        // X tile (float4 coalesced), optional fused ReLU
        for (int i = tid; i < RPB * (KT / 4); i += 256) {
            int r = i / (KT / 4), kg = i % (KT / 4);
            float4 v;
            if (row0 + r < n_rows)
                v = *(const float4*)&X[(long long)(row0 + r) * K + k0 + kg * 4];
            else
                v = make_float4(0.f, 0.f, 0.f, 0.f);
            if (RELU) {
                v.x = fmaxf(v.x, 0.f); v.y = fmaxf(v.y, 0.f);
                v.z = fmaxf(v.z, 0.f); v.w = fmaxf(v.w, 0.f);
            }
            *(float4*)&sX[r][kg * 4] = v;
        }
        __syncthreads();

#pragma unroll
        for (int kg = 0; kg < KT / 4; kg++) {            // 4 k's per step
            ulonglong2 w = *(const ulonglong2*)&sWTp[col][kg * 2];
#pragma unroll
            for (int j = 0; j < RPT; j++) {
                ulonglong2 x =
                    *(const ulonglong2*)&sX[slot * RPT + j][kg * 4];  // broadcast
                fma2(acc[j], x.x, w.x);
                fma2(acc[j], x.y, w.y);
            }
        }
        __syncthreads();
    }

#pragma unroll
    for (int j = 0; j < RPT; j++) {
        int r = row0 + slot * RPT + j;
        if (r < n_rows) {
            float lo, hi;
            asm("mov.b64 {%0, %1}, %2;" : "=f"(lo), "=f"(hi) : "l"(acc[j]));
            out[(long long)r * NCOL + col] = lo + hi;
        }
    }
}

__global__ __launch_bounds__(256) void gemm1_kernel(const float* __restrict__ X,
                                                    const float* __restrict__ W,
                                                    int n_rows) {
    gemm_body<256, HID, false>(X, W, g_support1, n_rows);
}

__global__ __launch_bounds__(256) void gemm2_kernel(const float* __restrict__ W,
                                                    int n_rows) {
    gemm_body<HID, ODIM, true>(g_h1, W, g_support2, n_rows);
}

// ---------------------------------------------------------------------------
// CSR gather-aggregate. NPW nodes/warp, 32/NPW lanes per node, float4/lane.
// Register accumulator, one coalesced write per row, x2 unroll for MLP.
// ---------------------------------------------------------------------------
template <int NCOL, int NPW>
__device__ __forceinline__ void gather_body(const float* __restrict__ src,
                                            float* __restrict__ dst, int n_nodes) {
    constexpr int LPN = 32 / NPW;
    const int lane = threadIdx.x & 31;
    const int wid = (blockIdx.x * blockDim.x + threadIdx.x) >> 5;
    const int node = wid * NPW + lane / LPN;
    const int part = lane % LPN;
    if (node >= n_nodes) return;

    const int beg = g_rowptr[node];
    const int end = g_rowptr[node + 1];

    float4 acc = make_float4(0.f, 0.f, 0.f, 0.f);
    const float4* s4 = (const float4*)src;
    constexpr int F4 = NCOL / 4;

    int i = beg;
    for (; i + 2 <= end; i += 2) {
        int c0 = __ldg(&g_colidx[i]);
        int c1 = __ldg(&g_colidx[i + 1]);
        float4 a = __ldg(&s4[(long long)c0 * F4 + part]);
        float4 b = __ldg(&s4[(long long)c1 * F4 + part]);
        acc.x += a.x + b.x; acc.y += a.y + b.y;
        acc.z += a.z + b.z; acc.w += a.w + b.w;
    }
    if (i < end) {
        int c0 = __ldg(&g_colidx[i]);
        float4 a = __ldg(&s4[(long long)c0 * F4 + part]);
        acc.x += a.x; acc.y += a.y; acc.z += a.z; acc.w += a.w;
    }
    ((float4*)dst)[(long long)node * F4 + part] = acc;
}

__global__ __launch_bounds__(256) void gather1_kernel(int n_nodes) {
    gather_body<HID, 1>(g_support1, g_h1, n_nodes);
}

__global__ __launch_bounds__(256) void gather2_kernel(float* __restrict__ out,
                                                      int n_nodes) {
    gather_body<ODIM, 2>(g_support2, out, n_nodes);
}

// ---------------------------------------------------------------------------
// launch
// ---------------------------------------------------------------------------
extern "C" void kernel_launch(void* const* d_in, const int* in_sizes, int n_in,
                              void* d_out, int out_size) {
    const float* features = (const float*)d_in[0];
    const void*  edges    = d_in[1];
    const float* W1       = (const float*)d_in[2];
    const float* W2       = (const float*)d_in[3];
    float*       out      = (float*)d_out;

    const int n_nodes = in_sizes[0] / 256;                 // 100000
    const long long n_edges = (long long)in_sizes[1] / 2;  // 3200000

    // --- CSR build -------------------------------------------------------
    detect_kernel<<<1, 1>>>((const unsigned int*)edges, 512);
    zero_count_kernel<<<(n_nodes + 255) / 256, 256>>>(n_nodes);
    hist_kernel<<<1184, 256>>>(edges, n_edges);
    scan_kernel<<<1, 1024>>>(n_nodes);
    fill_kernel<<<1184, 256>>>(edges, n_edges);

    const int gblocks = (n_nodes + 31) / 32;

    // --- layer 1 ---------------------------------------------------------
    gemm1_kernel<<<gblocks, 256>>>(features, W1, n_nodes);
    gather1_kernel<<<(n_nodes + 7) / 8, 256>>>(n_nodes);        // 1 node/warp

    // --- layer 2 ---------------------------------------------------------
    gemm2_kernel<<<gblocks, 256>>>(W2, n_nodes);
    gather2_kernel<<<(n_nodes + 15) / 16, 256>>>(out, n_nodes); // 2 nodes/warp
}

// round 14
// speedup vs baseline: 1.2917x; 1.2917x over previous
#include <cuda_runtime.h>
#include <cstdint>

// ---------------------------------------------------------------------------
// GCN 2-layer:  out = scatter_sum( relu( scatter_sum( X@W1 ) ) @ W2 )
//   X: [100000, 256] f32, edges: [2, 3200000] (int64 or int32),
//   W1: [256,128], W2: [128,64], out: [100000, 64] f32
//
// Design: CSR build (hist / 3-phase scan / fill) -> packed-f32x2 GEMM ->
// warp-gather aggregation (register accumulators, no float atomics).
// ---------------------------------------------------------------------------

#define MAX_NODES 100000
#define MAX_EDGES 3200000
#define HID 128
#define ODIM 64
#define SCAN_B 1024
#define MAX_SBLK 128   // ceil(100000/1024) = 98 <= 128

// Scratch (device globals: no allocation allowed)
__device__ __align__(16) float g_support1[(size_t)MAX_NODES * HID];   // X@W1
__device__ __align__(16) float g_h1[(size_t)MAX_NODES * HID];         // agg layer 1
__device__ __align__(16) float g_support2[(size_t)MAX_NODES * ODIM];  // relu(h1)@W2
__device__ int g_count[MAX_NODES];
__device__ int g_rowptr[MAX_NODES + 1];
__device__ int g_cursor[MAX_NODES];
__device__ int g_colidx[MAX_EDGES];
__device__ int g_blocksum[MAX_SBLK];
__device__ int g_blockoff[MAX_SBLK];
__device__ int g_is_i64;

// ---------------------------------------------------------------------------
// dtype detect (warp-parallel): int64 edges have all-zero high words
// ---------------------------------------------------------------------------
__global__ void detect_kernel(const unsigned int* __restrict__ w, int nwords) {
    int lane = threadIdx.x;
    unsigned int bad = 0;
    for (int i = lane * 2 + 1; i < nwords; i += 64) bad |= __ldg(&w[i]);
    unsigned int any = __any_sync(0xFFFFFFFFu, bad != 0u);
    if (lane == 0) g_is_i64 = any ? 0 : 1;
}

__global__ void zero_count_kernel(int n) {
    int i = blockIdx.x * blockDim.x + threadIdx.x;
    if (i < n) g_count[i] = 0;
}

// ---------------------------------------------------------------------------
// CSR build: histogram
// ---------------------------------------------------------------------------
__global__ __launch_bounds__(256) void hist_kernel(const void* __restrict__ eptr,
                                                   long long n_edges) {
    long long i = (long long)blockIdx.x * blockDim.x + threadIdx.x;
    long long stride = (long long)gridDim.x * blockDim.x;
    if (g_is_i64) {
        const long long* E = (const long long*)eptr;
        for (; i < n_edges; i += stride) atomicAdd(&g_count[(int)E[i]], 1);
    } else {
        const int* E = (const int*)eptr;
        for (; i < n_edges; i += stride) atomicAdd(&g_count[E[i]], 1);
    }
}

// ---------------------------------------------------------------------------
// 3-phase exclusive scan of g_count -> g_rowptr (+ cursor init)
// ---------------------------------------------------------------------------
// Phase 1: per-block exclusive scan (1024 elts/block), store block totals.
__global__ __launch_bounds__(SCAN_B) void scan_blocks_kernel(int n) {
    __shared__ int warpsum[32];
    const int t = threadIdx.x;
    const int i = blockIdx.x * SCAN_B + t;
    const int lane = t & 31, wid = t >> 5;

    int v = (i < n) ? g_count[i] : 0;
    int x = v;  // inclusive within warp
#pragma unroll
    for (int off = 1; off < 32; off <<= 1) {
        int y = __shfl_up_sync(0xFFFFFFFFu, x, off);
        if (lane >= off) x += y;
    }
    if (lane == 31) warpsum[wid] = x;
    __syncthreads();
    if (wid == 0) {
        int s = warpsum[lane];
#pragma unroll
        for (int off = 1; off < 32; off <<= 1) {
            int y = __shfl_up_sync(0xFFFFFFFFu, s, off);
            if (lane >= off) s += y;
        }
        warpsum[lane] = s;  // inclusive scan of warp sums
    }
    __syncthreads();
    int warpoff = (wid > 0) ? warpsum[wid - 1] : 0;
    if (i < n) g_rowptr[i] = warpoff + x - v;  // block-local exclusive
    if (t == 0) g_blocksum[blockIdx.x] = warpsum[31];
}

// Phase 2: scan block totals (single small block).
__global__ __launch_bounds__(MAX_SBLK) void scan_tops_kernel(int nblocks, int n) {
    __shared__ int ws[4];
    const int t = threadIdx.x;
    const int lane = t & 31, wid = t >> 5;

    int v = (t < nblocks) ? g_blocksum[t] : 0;
    int x = v;
#pragma unroll
    for (int off = 1; off < 32; off <<= 1) {
        int y = __shfl_up_sync(0xFFFFFFFFu, x, off);
        if (lane >= off) x += y;
    }
    if (lane == 31) ws[wid] = x;
    __syncthreads();
    if (t == 0) {
        int s = 0;
#pragma unroll
        for (int w = 0; w < 4; w++) { int tmp = ws[w]; ws[w] = s; s += tmp; }
    }
    __syncthreads();
    int incl = ws[wid] + x;
    if (t < nblocks) g_blockoff[t] = incl - v;   // exclusive block offset
    if (t == nblocks - 1) g_rowptr[n] = incl;    // grand total
}

// Phase 3: add block offsets; init cursors.
__global__ __launch_bounds__(SCAN_B) void scan_add_kernel(int n) {
    int i = blockIdx.x * SCAN_B + threadIdx.x;
    if (i < n) {
        int v = g_rowptr[i] + g_blockoff[blockIdx.x];
        g_rowptr[i] = v;
        g_cursor[i] = v;
    }
}

// ---------------------------------------------------------------------------
// CSR build: fill
// ---------------------------------------------------------------------------
__global__ __launch_bounds__(256) void fill_kernel(const void* __restrict__ eptr,
                                                   long long n_edges) {
    long long i = (long long)blockIdx.x * blockDim.x + threadIdx.x;
    long long stride = (long long)gridDim.x * blockDim.x;
    if (g_is_i64) {
        const long long* E = (const long long*)eptr;
        for (; i < n_edges; i += stride) {
            int row = (int)E[i];
            int col = (int)E[n_edges + i];
            g_colidx[atomicAdd(&g_cursor[row], 1)] = col;
        }
    } else {
        const int* E = (const int*)eptr;
        for (; i < n_edges; i += stride) {
            int row = E[i];
            int col = E[n_edges + i];
            g_colidx[atomicAdd(&g_cursor[row], 1)] = col;
        }
    }
}

// ---------------------------------------------------------------------------
// Packed-f32x2 GEMM: out[n_rows, NCOL] = act(X[n_rows, K]) @ W[K, NCOL]
// K packed pairwise into 64-bit lanes; one fma.rn.f32x2 per 2 scalar FMAs;
// lo+hi summed at epilogue. No pack instructions in the inner loop.
// ---------------------------------------------------------------------------
__device__ __forceinline__ void fma2(unsigned long long& acc,
                                     unsigned long long a,
                                     unsigned long long b) {
    asm("fma.rn.f32x2 %0, %1, %2, %0;" : "+l"(acc) : "l"(a), "l"(b));
}

template <int K, int NCOL, bool RELU>
__device__ __forceinline__ void gemm_body(const float* __restrict__ X,
                                          const float* __restrict__ W,
                                          float* __restrict__ out, int n_rows) {
    constexpr int KT = 64;                 // k-tile (32 pairs)
    constexpr int RPB = 32;                // rows per block
    constexpr int SLOTS = 256 / NCOL;
    constexpr int RPT = RPB / SLOTS;
    constexpr int WROW = KT / 2 + 2;       // 34 ull, conflict-free stride

    __shared__ float sX[RPB][KT];
    __shared__ unsigned long long sWTp[NCOL][WROW];

    const int tid = threadIdx.x;
    const int col = tid % NCOL;
    const int slot = tid / NCOL;
    const int row0 = blockIdx.x * RPB;

    unsigned long long acc[RPT];
#pragma unroll
    for (int j = 0; j < RPT; j++) acc[j] = 0ull;

    for (int k0 = 0; k0 < K; k0 += KT) {
        for (int i = tid; i < (KT / 2) * NCOL; i += 256) {
            int t = i / NCOL, c = i % NCOL;
            float w0 = W[(k0 + 2 * t) * NCOL + c];
            float w1 = W[(k0 + 2 * t + 1) * NCOL + c];
            unsigned long long p;
            asm("mov.b64 %0, {%1, %2};" : "=l"(p)
                : "r"(__float_as_uint(w0)), "r"(__float_as_uint(w1)));
            sWTp[c][t] = p;
        }
        for (int i = tid; i < RPB * (KT / 4); i += 256) {
            int r = i / (KT / 4), kg = i % (KT / 4);
            float4 v;
            if (row0 + r < n_rows)
                v = *(const float4*)&X[(long long)(row0 + r) * K + k0 + kg * 4];
            else
                v = make_float4(0.f, 0.f, 0.f, 0.f);
            if (RELU) {
                v.x = fmaxf(v.x, 0.f); v.y = fmaxf(v.y, 0.f);
                v.z = fmaxf(v.z, 0.f); v.w = fmaxf(v.w, 0.f);
            }
            *(float4*)&sX[r][kg * 4] = v;
        }
        __syncthreads();

#pragma unroll
        for (int kg = 0; kg < KT / 4; kg++) {
            ulonglong2 w = *(const ulonglong2*)&sWTp[col][kg * 2];
#pragma unroll
            for (int j = 0; j < RPT; j++) {
                ulonglong2 x =
                    *(const ulonglong2*)&sX[slot * RPT + j][kg * 4];
                fma2(acc[j], x.x, w.x);
                fma2(acc[j], x.y, w.y);
            }
        }
        __syncthreads();
    }

#pragma unroll
    for (int j = 0; j < RPT; j++) {
        int r = row0 + slot * RPT + j;
        if (r < n_rows) {
            float lo, hi;
            asm("mov.b64 {%0, %1}, %2;" : "=f"(lo), "=f"(hi) : "l"(acc[j]));
            out[(long long)r * NCOL + col] = lo + hi;
        }
    }
}

__global__ __launch_bounds__(256) void gemm1_kernel(const float* __restrict__ X,
                                                    const float* __restrict__ W,
                                                    int n_rows) {
    gemm_body<256, HID, false>(X, W, g_support1, n_rows);
}

__global__ __launch_bounds__(256) void gemm2_kernel(const float* __restrict__ W,
                                                    int n_rows) {
    gemm_body<HID, ODIM, true>(g_h1, W, g_support2, n_rows);
}

// ---------------------------------------------------------------------------
// CSR gather-aggregate. NPW nodes/warp, 32/NPW lanes per node, float4/lane.
// x4 unroll: 4 independent in-flight float4 loads per lane (MLP).
// ---------------------------------------------------------------------------
template <int NCOL, int NPW>
__device__ __forceinline__ void gather_body(const float* __restrict__ src,
                                            float* __restrict__ dst, int n_nodes) {
    constexpr int LPN = 32 / NPW;
    const int lane = threadIdx.x & 31;
    const int wid = (blockIdx.x * blockDim.x + threadIdx.x) >> 5;
    const int node = wid * NPW + lane / LPN;
    const int part = lane % LPN;
    if (node >= n_nodes) return;

    const int beg = g_rowptr[node];
    const int end = g_rowptr[node + 1];

    float4 acc0 = make_float4(0.f, 0.f, 0.f, 0.f);
    float4 acc1 = make_float4(0.f, 0.f, 0.f, 0.f);
    const float4* s4 = (const float4*)src;
    constexpr int F4 = NCOL / 4;

    int i = beg;
    for (; i + 4 <= end; i += 4) {
        int c0 = __ldg(&g_colidx[i]);
        int c1 = __ldg(&g_colidx[i + 1]);
        int c2 = __ldg(&g_colidx[i + 2]);
        int c3 = __ldg(&g_colidx[i + 3]);
        float4 a = __ldg(&s4[(long long)c0 * F4 + part]);
        float4 b = __ldg(&s4[(long long)c1 * F4 + part]);
        float4 c = __ldg(&s4[(long long)c2 * F4 + part]);
        float4 d = __ldg(&s4[(long long)c3 * F4 + part]);
        acc0.x += a.x + b.x; acc0.y += a.y + b.y;
        acc0.z += a.z + b.z; acc0.w += a.w + b.w;
        acc1.x += c.x + d.x; acc1.y += c.y + d.y;
        acc1.z += c.z + d.z; acc1.w += c.w + d.w;
    }
    for (; i < end; i++) {
        int c0 = __ldg(&g_colidx[i]);
        float4 a = __ldg(&s4[(long long)c0 * F4 + part]);
        acc0.x += a.x; acc0.y += a.y; acc0.z += a.z; acc0.w += a.w;
    }
    acc0.x += acc1.x; acc0.y += acc1.y; acc0.z += acc1.z; acc0.w += acc1.w;
    ((float4*)dst)[(long long)node * F4 + part] = acc0;
}

__global__ __launch_bounds__(256) void gather1_kernel(int n_nodes) {
    gather_body<HID, 1>(g_support1, g_h1, n_nodes);
}

__global__ __launch_bounds__(256) void gather2_kernel(float* __restrict__ out,
                                                      int n_nodes) {
    gather_body<ODIM, 2>(g_support2, out, n_nodes);
}

// ---------------------------------------------------------------------------
// launch
// ---------------------------------------------------------------------------
extern "C" void kernel_launch(void* const* d_in, const int* in_sizes, int n_in,
                              void* d_out, int out_size) {
    const float* features = (const float*)d_in[0];
    const void*  edges    = d_in[1];
    const float* W1       = (const float*)d_in[2];
    const float* W2       = (const float*)d_in[3];
    float*       out      = (float*)d_out;

    const int n_nodes = in_sizes[0] / 256;                 // 100000
    const long long n_edges = (long long)in_sizes[1] / 2;  // 3200000

    const int sblocks = (n_nodes + SCAN_B - 1) / SCAN_B;   // 98

    // --- CSR build -------------------------------------------------------
    detect_kernel<<<1, 32>>>((const unsigned int*)edges, 512);
    zero_count_kernel<<<(n_nodes + 255) / 256, 256>>>(n_nodes);
    hist_kernel<<<1184, 256>>>(edges, n_edges);
    scan_blocks_kernel<<<sblocks, SCAN_B>>>(n_nodes);
    scan_tops_kernel<<<1, MAX_SBLK>>>(sblocks, n_nodes);
    scan_add_kernel<<<sblocks, SCAN_B>>>(n_nodes);
    fill_kernel<<<1184, 256>>>(edges, n_edges);

    const int gblocks = (n_nodes + 31) / 32;

    // --- layer 1 ---------------------------------------------------------
    gemm1_kernel<<<gblocks, 256>>>(features, W1, n_nodes);
    gather1_kernel<<<(n_nodes + 7) / 8, 256>>>(n_nodes);        // 1 node/warp

    // --- layer 2 ---------------------------------------------------------
    gemm2_kernel<<<gblocks, 256>>>(W2, n_nodes);
    gather2_kernel<<<(n_nodes + 15) / 16, 256>>>(out, n_nodes); // 2 nodes/warp
}